// round 13
// baseline (speedup 1.0000x reference)
#include <cuda_runtime.h>
#include <cuda_fp16.h>
#include <stdint.h>
#include <math.h>

#define BB 64
#define FF 128
#define SS 2048
#define FS (FF*SS)        // 262144
#define MR (BB*FF)        // 8192

// ---------------- scratch ----------------
__device__ float g_stats3[3*BB*384];
__device__ float g_w3[3*BB];
__device__ __half g_pa0[MR*256];
__device__ __half g_pm0[MR*256];
__device__ __half g_pa1[MR*512];
__device__ __half g_pm1[MR*512];
__device__ __half g_pa2[MR*1024];
__device__ __half g_pm2[MR*1024];
__device__ __half g_ha0[MR*256];
__device__ __half g_ha1[MR*512];
__device__ __half g_ha2[MR*1024];
__device__ __half g_hh [MR*1024];
__device__ __half g_hx [MR*2048];   // normalized x, half (final residual base)
__device__ __half g_hw [4128768];   // 6 weights, transposed [N][K], half

// ---------------- fused batchnorm (stats+apply) + pooling + row stats ----------------
// one block per feature-row f (128 blocks). Thread t owns S-positions [t*8, t*8+8).
// Pass 1 computes per-position batch stats in registers; pass 2 (L2-resident)
// normalizes, writes hx + pools (half) + per-(b,f) pfs stats.
__global__ void __launch_bounds__(256) k_bnfused(const float* __restrict__ x,
        const float* __restrict__ gamma, const float* __restrict__ beta){
    int f = blockIdx.x, t = threadIdx.x;
    int base = f*2048 + t*8;

    float4 ga0 = *(const float4*)(gamma + base), ga1 = *(const float4*)(gamma + base + 4);
    float4 be0 = *(const float4*)(beta  + base), be1 = *(const float4*)(beta  + base + 4);
    float ga[8] = {ga0.x,ga0.y,ga0.z,ga0.w, ga1.x,ga1.y,ga1.z,ga1.w};
    float be[8] = {be0.x,be0.y,be0.z,be0.w, be1.x,be1.y,be1.z,be1.w};

    // pass 1: batch stats per position
    float s[8], q[8];
    #pragma unroll
    for (int j = 0; j < 8; j++){ s[j] = 0.f; q[j] = 0.f; }
    for (int b = 0; b < BB; b += 4){
        #pragma unroll
        for (int u = 0; u < 4; u++){
            const float* p = x + (size_t)(b+u)*FS + base;
            float4 v0 = *(const float4*)p, v1 = *(const float4*)(p + 4);
            float vv[8] = {v0.x,v0.y,v0.z,v0.w, v1.x,v1.y,v1.z,v1.w};
            #pragma unroll
            for (int j = 0; j < 8; j++){ s[j] += vv[j]; q[j] = fmaf(vv[j], vv[j], q[j]); }
        }
    }
    float mu[8], rs[8];
    #pragma unroll
    for (int j = 0; j < 8; j++){
        mu[j] = s[j]*(1.0f/BB);
        rs[j] = rsqrtf(fmaf(-mu[j], mu[j], q[j]*(1.0f/BB)) + 1e-5f);
    }

    __shared__ float red[8][9];
    int w = t >> 5, l = t & 31;

    // pass 2: normalize (L2 hits), pools, hx, per-(b,f) stats
    for (int b = 0; b < BB; b++){
        const float* p = x + (size_t)b*FS + base;
        float4 v0 = *(const float4*)p, v1 = *(const float4*)(p + 4);
        float raw[8] = {v0.x,v0.y,v0.z,v0.w, v1.x,v1.y,v1.z,v1.w};
        float v[8];
        #pragma unroll
        for (int j = 0; j < 8; j++)
            v[j] = fmaf((raw[j] - mu[j])*rs[j], ga[j], be[j]);

        int row = b*FF + f;
        // hx (half)
        {
            __half2 h0 = __floats2half2_rn(v[0],v[1]), h1 = __floats2half2_rn(v[2],v[3]);
            __half2 h2 = __floats2half2_rn(v[4],v[5]), h3 = __floats2half2_rn(v[6],v[7]);
            *(uint4*)(g_hx + (size_t)row*2048 + t*8) =
                make_uint4(*(unsigned*)&h0, *(unsigned*)&h1, *(unsigned*)&h2, *(unsigned*)&h3);
        }
        // pools
        float a2[4], m2[4];
        #pragma unroll
        for (int j = 0; j < 4; j++){
            a2[j] = 0.5f*(v[2*j] + v[2*j+1]);
            m2[j] = fmaxf(v[2*j], v[2*j+1]);
        }
        float a1[2], m1[2];
        #pragma unroll
        for (int j = 0; j < 2; j++){
            a1[j] = 0.5f*(a2[2*j] + a2[2*j+1]);
            m1[j] = fmaxf(m2[2*j], m2[2*j+1]);
        }
        float a0 = 0.5f*(a1[0] + a1[1]);
        float m0 = fmaxf(m1[0], m1[1]);
        {
            __half2 q0 = __floats2half2_rn(a2[0],a2[1]), q1 = __floats2half2_rn(a2[2],a2[3]);
            *(uint2*)(g_pa2 + (size_t)row*1024 + t*4) = make_uint2(*(unsigned*)&q0, *(unsigned*)&q1);
            __half2 r0 = __floats2half2_rn(m2[0],m2[1]), r1 = __floats2half2_rn(m2[2],m2[3]);
            *(uint2*)(g_pm2 + (size_t)row*1024 + t*4) = make_uint2(*(unsigned*)&r0, *(unsigned*)&r1);
            __half2 s1h = __floats2half2_rn(a1[0],a1[1]);
            *(unsigned*)(g_pa1 + (size_t)row*512 + t*2) = *(unsigned*)&s1h;
            __half2 u1h = __floats2half2_rn(m1[0],m1[1]);
            *(unsigned*)(g_pm1 + (size_t)row*512 + t*2) = *(unsigned*)&u1h;
            g_pa0[(size_t)row*256 + t] = __float2half(a0);
            g_pm0[(size_t)row*256 + t] = __float2half(m0);
        }

        // pfs stats for this (b,f) row
        float su[3], sq[3], mx[3];
        {
            float pv = 0.5f*(a0 + m0);
            su[0] = pv; sq[0] = pv*pv; mx[0] = pv;
        }
        su[1] = 0.f; sq[1] = 0.f; mx[1] = -3.4e38f;
        #pragma unroll
        for (int j = 0; j < 2; j++){
            float pv = 0.5f*(a1[j] + m1[j]);
            su[1] += pv; sq[1] = fmaf(pv, pv, sq[1]); mx[1] = fmaxf(mx[1], pv);
        }
        su[2] = 0.f; sq[2] = 0.f; mx[2] = -3.4e38f;
        #pragma unroll
        for (int j = 0; j < 4; j++){
            float pv = 0.5f*(a2[j] + m2[j]);
            su[2] += pv; sq[2] = fmaf(pv, pv, sq[2]); mx[2] = fmaxf(mx[2], pv);
        }
        #pragma unroll
        for (int sc = 0; sc < 3; sc++){
            #pragma unroll
            for (int o = 16; o > 0; o >>= 1){
                su[sc] += __shfl_down_sync(0xffffffffu, su[sc], o);
                sq[sc] += __shfl_down_sync(0xffffffffu, sq[sc], o);
                mx[sc]  = fmaxf(mx[sc], __shfl_down_sync(0xffffffffu, mx[sc], o));
            }
        }
        if (l == 0){
            #pragma unroll
            for (int sc = 0; sc < 3; sc++){
                red[w][sc*3] = su[sc]; red[w][sc*3+1] = sq[sc]; red[w][sc*3+2] = mx[sc];
            }
        }
        __syncthreads();
        if (t < 3){
            int sc = t;
            float S = 0.f, Q = 0.f, M = -3.4e38f;
            #pragma unroll
            for (int ww = 0; ww < 8; ww++){
                S += red[ww][sc*3]; Q += red[ww][sc*3+1]; M = fmaxf(M, red[ww][sc*3+2]);
            }
            int L = 256 << sc;
            float mean = S / (float)L;
            float var  = (Q - (float)L*mean*mean) / (float)(L - 1);
            float sd   = sqrtf(fmaxf(var, 0.f));
            float* st = g_stats3 + sc*BB*384 + b*384;
            st[f] = mean; st[128 + f] = sd; st[256 + f] = M;
        }
        __syncthreads();
    }
}

// ---------------- fused selector MLPs ----------------
__global__ void k_selector3(const float* w1a, const float* w1b, const float* w1c,
                            const float* b1a, const float* b1b, const float* b1c,
                            const float* w2a, const float* w2b, const float* w2c,
                            const float* b2a, const float* b2b, const float* b2c){
    int s = blockIdx.x >> 6, b = blockIdx.x & 63, t = threadIdx.x;
    const float* w1 = s==0 ? w1a : (s==1 ? w1b : w1c);
    const float* b1 = s==0 ? b1a : (s==1 ? b1b : b1c);
    const float* w2 = s==0 ? w2a : (s==1 ? w2b : w2c);
    const float* b2 = s==0 ? b2a : (s==1 ? b2b : b2c);
    const float* st = g_stats3 + s*BB*384 + b*384;
    float acc = b1[t];
    #pragma unroll 8
    for (int i = 0; i < 384; i++) acc = fmaf(st[i], w1[i*64 + t], acc);
    float hv = fmaxf(acc, 0.f) * w2[t];
    __shared__ float red[64];
    red[t] = hv;
    __syncthreads();
    if (t < 32){
        float v = red[t] + red[t + 32];
        #pragma unroll
        for (int o = 16; o > 0; o >>= 1) v += __shfl_down_sync(0xffffffffu, v, o);
        if (t == 0) g_w3[s*64 + b] = 1.0f / (1.0f + expf(-(v + b2[0])));
    }
}

// ---------------- blend s0 only (half2) ----------------
__global__ void k_blend0(){
    int i = blockIdx.x*blockDim.x + threadIdx.x;    // over MR*128 half2
    float w = g_w3[i >> 14];
    float2 af = __half22float2(((const __half2*)g_pa0)[i]);
    float2 mf = __half22float2(((const __half2*)g_pm0)[i]);
    ((__half2*)g_ha0)[i] =
        __floats2half2_rn(fmaf(w, af.x - mf.x, mf.x), fmaf(w, af.y - mf.y, mf.y));
}

// ---------------- weight transpose+convert: fp32 [K][N] -> half [N][K] ----------------
__global__ void k_wtrans_all(const float* w0, const float* w1, const float* w2,
                             const float* w3, const float* w4, const float* w5){
    __shared__ float sm[32][33];
    int blk = blockIdx.x;
    const float* in; __half* outp; int K, N, rem;
    if      (blk <   64){ in = w0; outp = g_hw;           K =  256; N =  256; rem = blk; }
    else if (blk <  192){ in = w1; outp = g_hw +   65536; K =  256; N =  512; rem = blk -   64; }
    else if (blk <  448){ in = w2; outp = g_hw +  196608; K =  512; N =  512; rem = blk -  192; }
    else if (blk <  960){ in = w3; outp = g_hw +  458752; K =  512; N = 1024; rem = blk -  448; }
    else if (blk < 1984){ in = w4; outp = g_hw +  983040; K = 1024; N = 1024; rem = blk -  960; }
    else                { in = w5; outp = g_hw + 2031616; K = 1024; N = 2048; rem = blk - 1984; }
    int tn = rem % (N/32), tk = rem / (N/32);
    int n0 = tn*32, k0 = tk*32;
    int tx = threadIdx.x, ty = threadIdx.y;
    #pragma unroll
    for (int j = 0; j < 4; j++)
        sm[ty + j*8][tx] = in[(size_t)(k0 + ty + j*8)*N + n0 + tx];
    __syncthreads();
    #pragma unroll
    for (int j = 0; j < 4; j++)
        outp[(size_t)(n0 + ty + j*8)*K + k0 + tx] = __float2half(sm[tx][ty + j*8]);
}

// ---------------- fp16 tensor-core GEMM ----------------
// CTA TM x 128, 256 threads (8 warps), BK=64 halves, XOR-swizzled 128B rows,
// ST-stage cp.async pipeline, one barrier per k-tile.
// mode 0: Ch = half(gelu(v+bias))
// mode 1: Ch = half(blend(Pa,Pm,wsel) + v + bias)
// mode 2: Cf = float(Rh) + v + bias

__device__ __forceinline__ void cp16(unsigned int s, const void* g){
    asm volatile("cp.async.cg.shared.global [%0], [%1], 16;\n" :: "r"(s), "l"(g));
}
__device__ __forceinline__ void ldm_x4(unsigned int* r, unsigned int a){
    asm volatile("ldmatrix.sync.aligned.m8n8.x4.shared.b16 {%0,%1,%2,%3}, [%4];"
                 : "=r"(r[0]), "=r"(r[1]), "=r"(r[2]), "=r"(r[3]) : "r"(a));
}
__device__ __forceinline__ void mma_f16(float* c, const unsigned int* a,
                                        unsigned int b0, unsigned int b1){
    asm volatile("mma.sync.aligned.m16n8k16.row.col.f32.f16.f16.f32 "
                 "{%0,%1,%2,%3}, {%4,%5,%6,%7}, {%8,%9}, {%0,%1,%2,%3};\n"
                 : "+f"(c[0]), "+f"(c[1]), "+f"(c[2]), "+f"(c[3])
                 : "r"(a[0]), "r"(a[1]), "r"(a[2]), "r"(a[3]), "r"(b0), "r"(b1));
}

template<int TM, int ST>
__global__ void __launch_bounds__(256, 2) k_hgemm(
        const __half* __restrict__ A, const __half* __restrict__ W,
        const float* __restrict__ bias,
        __half* __restrict__ Ch,
        const __half* __restrict__ Pa, const __half* __restrict__ Pm,
        const float* __restrict__ wsel,
        const __half* __restrict__ Rh, float* __restrict__ Cf,
        int K, int N, int mode){
    constexpr int WMC = TM/32;
    constexpr int WNC = 8/WMC;
    constexpr int NT  = 128/WNC;
    constexpr int NF  = NT/8;
    constexpr int NFP = NT/16;
    constexpr int BOFF = TM*128;
    constexpr int STAGE = (TM + 128)*128;

    extern __shared__ __align__(16) char smem[];
    unsigned int smb = (unsigned int)__cvta_generic_to_shared(smem);

    const int tid = threadIdx.x, lane = tid & 31, warp = tid >> 5;
    const int wm = warp % WMC, wn = warp / WMC;
    const int qid = lane >> 2, tig = lane & 3;
    const int m0 = blockIdx.y*TM, n0 = blockIdx.x*128;
    const int nkt = K >> 6;

    float acc[2][NF][4];
    #pragma unroll
    for (int mf = 0; mf < 2; mf++)
        #pragma unroll
        for (int nf = 0; nf < NF; nf++)
            #pragma unroll
            for (int r = 0; r < 4; r++) acc[mf][nf][r] = 0.f;

    unsigned int qa[2], qb[NFP];
    {
        int ar = wm*32 + (lane & 15);
        int ahi = (lane >> 4) & 1;
        #pragma unroll
        for (int mf = 0; mf < 2; mf++){
            int row = ar + mf*16;
            qa[mf] = (unsigned int)(row*128 + ((ahi << 4) ^ ((row & 7) << 4)));
        }
        int bn = wn*NT + (lane & 7) + ((lane >> 4) & 1)*8;
        int bhi = (lane >> 3) & 1;
        #pragma unroll
        for (int nfp = 0; nfp < NFP; nfp++){
            int row = bn + nfp*16;
            qb[nfp] = (unsigned int)(BOFF + row*128 + ((bhi << 4) ^ ((row & 7) << 4)));
        }
    }

    auto load_tile = [&](int kt, int st){
        unsigned int sb = smb + st*STAGE;
        const __half* Ab = A + (size_t)m0*K + kt*64;
        const __half* Wb = W + (size_t)n0*K + kt*64;
        #pragma unroll
        for (int it = 0; it < TM/32; it++){
            int idx = tid + it*256;
            int row = idx >> 3, c = idx & 7;
            cp16(sb + row*128 + ((c ^ (row & 7)) << 4), Ab + (size_t)row*K + c*8);
        }
        #pragma unroll
        for (int it = 0; it < 4; it++){
            int idx = tid + it*256;
            int row = idx >> 3, c = idx & 7;
            cp16(sb + BOFF + row*128 + ((c ^ (row & 7)) << 4), Wb + (size_t)row*K + c*8);
        }
        asm volatile("cp.async.commit_group;\n");
    };

    #pragma unroll
    for (int p = 0; p < ST-1; p++)
        if (p < nkt) load_tile(p, p);

    int st = 0;
    for (int kt = 0; kt < nkt; kt++){
        if (kt + ST-1 < nkt){
            asm volatile("cp.async.wait_group %0;\n" :: "n"(ST-2));
        } else {
            asm volatile("cp.async.wait_group %0;\n" :: "n"(0));
        }
        __syncthreads();
        if (kt + ST-1 < nkt){
            int s2 = st + ST-1; if (s2 >= ST) s2 -= ST;
            load_tile(kt + ST-1, s2);
        }

        unsigned int sb = smb + st*STAGE;
        #pragma unroll
        for (int ks = 0; ks < 4; ks++){
            unsigned int kx = (unsigned int)(ks << 5);
            unsigned int a[8], b[NFP*4];
            ldm_x4(a,     sb + (qa[0] ^ kx));
            ldm_x4(a + 4, sb + (qa[1] ^ kx));
            #pragma unroll
            for (int nfp = 0; nfp < NFP; nfp++)
                ldm_x4(b + nfp*4, sb + (qb[nfp] ^ kx));
            #pragma unroll
            for (int mf = 0; mf < 2; mf++)
                #pragma unroll
                for (int nf = 0; nf < NF; nf++)
                    mma_f16(acc[mf][nf], a + mf*4, b[nf*2], b[nf*2 + 1]);
        }
        if (++st == ST) st = 0;
    }

    // epilogue
    #pragma unroll
    for (int mf = 0; mf < 2; mf++){
        #pragma unroll
        for (int nf = 0; nf < NF; nf++){
            int col = n0 + wn*NT + nf*8 + tig*2;
            float2 bv = *(const float2*)(bias + col);
            #pragma unroll
            for (int h = 0; h < 2; h++){
                int row = m0 + wm*32 + mf*16 + qid + h*8;
                size_t idx = (size_t)row*N + col;
                float vx = acc[mf][nf][h*2 + 0] + bv.x;
                float vy = acc[mf][nf][h*2 + 1] + bv.y;
                if (mode == 0){
                    float ox = 0.5f*vx*(1.0f + erff(vx*0.70710678118f));
                    float oy = 0.5f*vy*(1.0f + erff(vy*0.70710678118f));
                    *(__half2*)(Ch + idx) = __floats2half2_rn(ox, oy);
                } else if (mode == 1){
                    float wv = wsel[row >> 7];
                    float2 af = __half22float2(*(const __half2*)(Pa + idx));
                    float2 mf2 = __half22float2(*(const __half2*)(Pm + idx));
                    float rx = fmaf(wv, af.x - mf2.x, mf2.x);
                    float ry = fmaf(wv, af.y - mf2.y, mf2.y);
                    *(__half2*)(Ch + idx) = __floats2half2_rn(rx + vx, ry + vy);
                } else {
                    float2 rf = __half22float2(*(const __half2*)(Rh + idx));
                    float2 o; o.x = rf.x + vx; o.y = rf.y + vy;
                    *(float2*)(Cf + idx) = o;
                }
            }
        }
    }
}

#define SMEM64  (4*((64 + 128)*128))    // 4-stage, 96KB
#define SMEM128 (3*((128 + 128)*128))   // 3-stage, 96KB

// ---------------- launch ----------------
extern "C" void kernel_launch(void* const* d_in, const int* in_sizes, int n_in,
                              void* d_out, int out_size){
    const float* x     = (const float*)d_in[0];
    const float* gamma = (const float*)d_in[1];
    const float* beta  = (const float*)d_in[2];
    float* out = (float*)d_out;

    cudaFuncSetAttribute((const void*)k_hgemm<64,4>,  cudaFuncAttributeMaxDynamicSharedMemorySize, SMEM64);
    cudaFuncSetAttribute((const void*)k_hgemm<128,3>, cudaFuncAttributeMaxDynamicSharedMemorySize, SMEM128);

    __half *ha0, *ha1, *ha2, *hh, *hx, *hw;
    __half *pa1, *pm1, *pa2, *pm2;
    float *w3;
    cudaGetSymbolAddress((void**)&ha0, g_ha0);
    cudaGetSymbolAddress((void**)&ha1, g_ha1);
    cudaGetSymbolAddress((void**)&ha2, g_ha2);
    cudaGetSymbolAddress((void**)&hh,  g_hh);
    cudaGetSymbolAddress((void**)&hx,  g_hx);
    cudaGetSymbolAddress((void**)&hw,  g_hw);
    cudaGetSymbolAddress((void**)&pa1, g_pa1);
    cudaGetSymbolAddress((void**)&pm1, g_pm1);
    cudaGetSymbolAddress((void**)&pa2, g_pa2);
    cudaGetSymbolAddress((void**)&pm2, g_pm2);
    cudaGetSymbolAddress((void**)&w3,  g_w3);
    static const size_t WOFF[6] = {0, 65536, 196608, 458752, 983040, 2031616};

    const float* lb1_0 = (const float*)d_in[3 + 0*8 + 5];
    const float* lb2_0 = (const float*)d_in[3 + 0*8 + 7];
    const float* lb1_1 = (const float*)d_in[3 + 1*8 + 5];
    const float* lb2_1 = (const float*)d_in[3 + 1*8 + 7];
    const float* lb1_2 = (const float*)d_in[3 + 2*8 + 5];
    const float* lb2_2 = (const float*)d_in[3 + 2*8 + 7];

    // launch 0: fused batchnorm + pools + stats
    k_bnfused<<<FF, 256>>>(x, gamma, beta);
    // launch 1: selectors
    k_selector3<<<192, 64>>>(
        (const float*)d_in[3 + 0*8 + 0], (const float*)d_in[3 + 1*8 + 0], (const float*)d_in[3 + 2*8 + 0],
        (const float*)d_in[3 + 0*8 + 1], (const float*)d_in[3 + 1*8 + 1], (const float*)d_in[3 + 2*8 + 1],
        (const float*)d_in[3 + 0*8 + 2], (const float*)d_in[3 + 1*8 + 2], (const float*)d_in[3 + 2*8 + 2],
        (const float*)d_in[3 + 0*8 + 3], (const float*)d_in[3 + 1*8 + 3], (const float*)d_in[3 + 2*8 + 3]);
    // launch 2: blend s0
    k_blend0<<<(MR*128)/256, 256>>>();
    // launch 3 (ncu capture slot): weights -> half [N][K]
    k_wtrans_all<<<4032, dim3(32, 8)>>>(
        (const float*)d_in[3 + 0*8 + 4], (const float*)d_in[3 + 0*8 + 6],
        (const float*)d_in[3 + 1*8 + 4], (const float*)d_in[3 + 1*8 + 6],
        (const float*)d_in[3 + 2*8 + 4], (const float*)d_in[3 + 2*8 + 6]);

    // GEMM chain
    k_hgemm<64,4> <<<dim3( 2, 128), 256, SMEM64 >>>(ha0, hw + WOFF[0], lb1_0, hh,  pa1, pm1, w3+64,  hx, out,  256,  256, 0);
    k_hgemm<64,4> <<<dim3( 4, 128), 256, SMEM64 >>>(hh,  hw + WOFF[1], lb2_0, ha1, pa1, pm1, w3+64,  hx, out,  256,  512, 1);
    k_hgemm<64,4> <<<dim3( 4, 128), 256, SMEM64 >>>(ha1, hw + WOFF[2], lb1_1, hh,  pa1, pm1, w3+64,  hx, out,  512,  512, 0);
    k_hgemm<128,3><<<dim3( 8,  64), 256, SMEM128>>>(hh,  hw + WOFF[3], lb2_1, ha2, pa2, pm2, w3+128, hx, out,  512, 1024, 1);
    k_hgemm<128,3><<<dim3( 8,  64), 256, SMEM128>>>(ha2, hw + WOFF[4], lb1_2, hh,  pa2, pm2, w3+128, hx, out, 1024, 1024, 0);
    k_hgemm<128,3><<<dim3(16,  64), 256, SMEM128>>>(hh,  hw + WOFF[5], lb2_2, hh,  pa2, pm2, w3+128, hx, out, 1024, 2048, 2);
}

// round 14
// speedup vs baseline: 1.0953x; 1.0953x over previous
#include <cuda_runtime.h>
#include <cuda_fp16.h>
#include <stdint.h>
#include <math.h>

#define BB 64
#define FF 128
#define SS 2048
#define FS (FF*SS)        // 262144
#define MR (BB*FF)        // 8192

// ---------------- scratch ----------------
__device__ float g_mu[FS];
__device__ float g_rstd[FS];
__device__ float g_stats3[3*BB*384];
__device__ float g_w3[3*BB];
__device__ __half g_pa0[MR*256];
__device__ __half g_pm0[MR*256];
__device__ __half g_pa1[MR*512];
__device__ __half g_pm1[MR*512];
__device__ __half g_pa2[MR*1024];
__device__ __half g_pm2[MR*1024];
__device__ __half g_ha1[MR*512];
__device__ __half g_ha2[MR*1024];
__device__ __half g_hh [MR*1024];
__device__ __half g_hx [MR*2048];   // normalized x, half (final residual base)
__device__ __half g_hw [4128768];   // 6 weights, transposed [N][K], half

// ---------------- batchnorm stats (float4) ----------------
__global__ void k_bnstats(const float4* __restrict__ x){
    int j = blockIdx.x*blockDim.x + threadIdx.x;     // over FS/4
    float4 s = make_float4(0,0,0,0), q = make_float4(0,0,0,0);
    #pragma unroll 4
    for (int b = 0; b < BB; b++){
        float4 v = x[(size_t)b*(FS/4) + j];
        s.x += v.x; s.y += v.y; s.z += v.z; s.w += v.w;
        q.x = fmaf(v.x, v.x, q.x); q.y = fmaf(v.y, v.y, q.y);
        q.z = fmaf(v.z, v.z, q.z); q.w = fmaf(v.w, v.w, q.w);
    }
    float4 mu, rs;
    mu.x = s.x*(1.0f/BB); mu.y = s.y*(1.0f/BB); mu.z = s.z*(1.0f/BB); mu.w = s.w*(1.0f/BB);
    rs.x = rsqrtf(fmaf(-mu.x, mu.x, q.x*(1.0f/BB)) + 1e-5f);
    rs.y = rsqrtf(fmaf(-mu.y, mu.y, q.y*(1.0f/BB)) + 1e-5f);
    rs.z = rsqrtf(fmaf(-mu.z, mu.z, q.z*(1.0f/BB)) + 1e-5f);
    rs.w = rsqrtf(fmaf(-mu.w, mu.w, q.w*(1.0f/BB)) + 1e-5f);
    ((float4*)g_mu)[j]   = mu;
    ((float4*)g_rstd)[j] = rs;
}

// ---------------- fused bnapply + pooling (half) + row stats ----------------
__global__ void __launch_bounds__(128) k_bnpool(const float* __restrict__ x,
        const float* __restrict__ gamma, const float* __restrict__ beta){
    int row = blockIdx.x, t = threadIdx.x;
    int b = row >> 7, f = row & 127;
    size_t gx = (size_t)b*FS + f*2048 + t*16;
    int    pj = f*2048 + t*16;

    float v[16];
    #pragma unroll
    for (int c = 0; c < 4; c++){
        float4 xv = *(const float4*)(x + gx + c*4);
        float4 mu = *(const float4*)(g_mu + pj + c*4);
        float4 rs = *(const float4*)(g_rstd + pj + c*4);
        float4 ga = *(const float4*)(gamma + pj + c*4);
        float4 be = *(const float4*)(beta + pj + c*4);
        v[c*4+0] = fmaf((xv.x - mu.x)*rs.x, ga.x, be.x);
        v[c*4+1] = fmaf((xv.y - mu.y)*rs.y, ga.y, be.y);
        v[c*4+2] = fmaf((xv.z - mu.z)*rs.z, ga.z, be.z);
        v[c*4+3] = fmaf((xv.w - mu.w)*rs.w, ga.w, be.w);
    }
    // normalized x -> half
    {
        __half2 h0 = __floats2half2_rn(v[0], v[1]),  h1 = __floats2half2_rn(v[2], v[3]);
        __half2 h2 = __floats2half2_rn(v[4], v[5]),  h3 = __floats2half2_rn(v[6], v[7]);
        __half2 h4 = __floats2half2_rn(v[8], v[9]),  h5 = __floats2half2_rn(v[10],v[11]);
        __half2 h6 = __floats2half2_rn(v[12],v[13]), h7 = __floats2half2_rn(v[14],v[15]);
        *(uint4*)(g_hx + (size_t)row*2048 + t*16)     =
            make_uint4(*(unsigned*)&h0, *(unsigned*)&h1, *(unsigned*)&h2, *(unsigned*)&h3);
        *(uint4*)(g_hx + (size_t)row*2048 + t*16 + 8) =
            make_uint4(*(unsigned*)&h4, *(unsigned*)&h5, *(unsigned*)&h6, *(unsigned*)&h7);
    }

    float a2[8], m2[8];
    #pragma unroll
    for (int j = 0; j < 8; j++){
        a2[j] = 0.5f*(v[2*j] + v[2*j+1]);
        m2[j] = fmaxf(v[2*j], v[2*j+1]);
    }
    float a1[4], m1[4];
    #pragma unroll
    for (int j = 0; j < 4; j++){
        a1[j] = 0.5f*(a2[2*j] + a2[2*j+1]);
        m1[j] = fmaxf(m2[2*j], m2[2*j+1]);
    }
    float a0[2], m0[2];
    #pragma unroll
    for (int j = 0; j < 2; j++){
        a0[j] = 0.5f*(a1[2*j] + a1[2*j+1]);
        m0[j] = fmaxf(m1[2*j], m1[2*j+1]);
    }

    {
        __half2 q0 = __floats2half2_rn(a2[0],a2[1]), q1 = __floats2half2_rn(a2[2],a2[3]);
        __half2 q2 = __floats2half2_rn(a2[4],a2[5]), q3 = __floats2half2_rn(a2[6],a2[7]);
        *(uint4*)(g_pa2 + (size_t)row*1024 + t*8) =
            make_uint4(*(unsigned*)&q0, *(unsigned*)&q1, *(unsigned*)&q2, *(unsigned*)&q3);
        __half2 r0 = __floats2half2_rn(m2[0],m2[1]), r1 = __floats2half2_rn(m2[2],m2[3]);
        __half2 r2 = __floats2half2_rn(m2[4],m2[5]), r3 = __floats2half2_rn(m2[6],m2[7]);
        *(uint4*)(g_pm2 + (size_t)row*1024 + t*8) =
            make_uint4(*(unsigned*)&r0, *(unsigned*)&r1, *(unsigned*)&r2, *(unsigned*)&r3);
        __half2 s0h = __floats2half2_rn(a1[0],a1[1]), s1h = __floats2half2_rn(a1[2],a1[3]);
        *(uint2*)(g_pa1 + (size_t)row*512 + t*4) = make_uint2(*(unsigned*)&s0h, *(unsigned*)&s1h);
        __half2 u0 = __floats2half2_rn(m1[0],m1[1]), u1 = __floats2half2_rn(m1[2],m1[3]);
        *(uint2*)(g_pm1 + (size_t)row*512 + t*4) = make_uint2(*(unsigned*)&u0, *(unsigned*)&u1);
        __half2 w0h = __floats2half2_rn(a0[0],a0[1]);
        *(unsigned*)(g_pa0 + (size_t)row*256 + t*2) = *(unsigned*)&w0h;
        __half2 w1h = __floats2half2_rn(m0[0],m0[1]);
        *(unsigned*)(g_pm0 + (size_t)row*256 + t*2) = *(unsigned*)&w1h;
    }

    float su[3] = {0,0,0}, sq[3] = {0,0,0}, mx[3] = {-3.4e38f,-3.4e38f,-3.4e38f};
    #pragma unroll
    for (int j = 0; j < 2; j++){ float pv = 0.5f*(a0[j]+m0[j]); su[0]+=pv; sq[0]=fmaf(pv,pv,sq[0]); mx[0]=fmaxf(mx[0],pv); }
    #pragma unroll
    for (int j = 0; j < 4; j++){ float pv = 0.5f*(a1[j]+m1[j]); su[1]+=pv; sq[1]=fmaf(pv,pv,sq[1]); mx[1]=fmaxf(mx[1],pv); }
    #pragma unroll
    for (int j = 0; j < 8; j++){ float pv = 0.5f*(a2[j]+m2[j]); su[2]+=pv; sq[2]=fmaf(pv,pv,sq[2]); mx[2]=fmaxf(mx[2],pv); }

    __shared__ float red[4][9];
    int w = t >> 5, l = t & 31;
    #pragma unroll
    for (int s = 0; s < 3; s++){
        #pragma unroll
        for (int o = 16; o > 0; o >>= 1){
            su[s] += __shfl_down_sync(0xffffffffu, su[s], o);
            sq[s] += __shfl_down_sync(0xffffffffu, sq[s], o);
            mx[s]  = fmaxf(mx[s], __shfl_down_sync(0xffffffffu, mx[s], o));
        }
    }
    if (l == 0){
        #pragma unroll
        for (int s = 0; s < 3; s++){ red[w][s*3] = su[s]; red[w][s*3+1] = sq[s]; red[w][s*3+2] = mx[s]; }
    }
    __syncthreads();
    if (t == 0){
        #pragma unroll
        for (int s = 0; s < 3; s++){
            float S = red[0][s*3] + red[1][s*3] + red[2][s*3] + red[3][s*3];
            float Q = red[0][s*3+1] + red[1][s*3+1] + red[2][s*3+1] + red[3][s*3+1];
            float M = fmaxf(fmaxf(red[0][s*3+2], red[1][s*3+2]), fmaxf(red[2][s*3+2], red[3][s*3+2]));
            int L = 256 << s;
            float mean = S / (float)L;
            float var  = (Q - (float)L*mean*mean) / (float)(L - 1);
            float sd   = sqrtf(fmaxf(var, 0.f));
            float* st = g_stats3 + s*BB*384 + b*384;
            st[f] = mean; st[128 + f] = sd; st[256 + f] = M;
        }
    }
}

// ---------------- fused selector MLPs ----------------
__global__ void k_selector3(const float* w1a, const float* w1b, const float* w1c,
                            const float* b1a, const float* b1b, const float* b1c,
                            const float* w2a, const float* w2b, const float* w2c,
                            const float* b2a, const float* b2b, const float* b2c){
    int s = blockIdx.x >> 6, b = blockIdx.x & 63, t = threadIdx.x;
    const float* w1 = s==0 ? w1a : (s==1 ? w1b : w1c);
    const float* b1 = s==0 ? b1a : (s==1 ? b1b : b1c);
    const float* w2 = s==0 ? w2a : (s==1 ? w2b : w2c);
    const float* b2 = s==0 ? b2a : (s==1 ? b2b : b2c);
    const float* st = g_stats3 + s*BB*384 + b*384;
    float acc = b1[t];
    #pragma unroll 8
    for (int i = 0; i < 384; i++) acc = fmaf(st[i], w1[i*64 + t], acc);
    float hv = fmaxf(acc, 0.f) * w2[t];
    __shared__ float red[64];
    red[t] = hv;
    __syncthreads();
    if (t < 32){
        float v = red[t] + red[t + 32];
        #pragma unroll
        for (int o = 16; o > 0; o >>= 1) v += __shfl_down_sync(0xffffffffu, v, o);
        if (t == 0) g_w3[s*64 + b] = 1.0f / (1.0f + expf(-(v + b2[0])));
    }
}

// ---------------- weight transpose+convert: fp32 [K][N] -> half [N][K] ----------------
__global__ void k_wtrans_all(const float* w0, const float* w1, const float* w2,
                             const float* w3, const float* w4, const float* w5){
    __shared__ float sm[32][33];
    int blk = blockIdx.x;
    const float* in; __half* outp; int K, N, rem;
    if      (blk <   64){ in = w0; outp = g_hw;           K =  256; N =  256; rem = blk; }
    else if (blk <  192){ in = w1; outp = g_hw +   65536; K =  256; N =  512; rem = blk -   64; }
    else if (blk <  448){ in = w2; outp = g_hw +  196608; K =  512; N =  512; rem = blk -  192; }
    else if (blk <  960){ in = w3; outp = g_hw +  458752; K =  512; N = 1024; rem = blk -  448; }
    else if (blk < 1984){ in = w4; outp = g_hw +  983040; K = 1024; N = 1024; rem = blk -  960; }
    else                { in = w5; outp = g_hw + 2031616; K = 1024; N = 2048; rem = blk - 1984; }
    int tn = rem % (N/32), tk = rem / (N/32);
    int n0 = tn*32, k0 = tk*32;
    int tx = threadIdx.x, ty = threadIdx.y;
    #pragma unroll
    for (int j = 0; j < 4; j++)
        sm[ty + j*8][tx] = in[(size_t)(k0 + ty + j*8)*N + n0 + tx];
    __syncthreads();
    #pragma unroll
    for (int j = 0; j < 4; j++)
        outp[(size_t)(n0 + ty + j*8)*K + k0 + tx] = __float2half(sm[tx][ty + j*8]);
}

// ---------------- fp16 tensor-core GEMM ----------------
// CTA TM x 128, 256 threads (8 warps), BK=64 halves, XOR-swizzled 128B rows,
// ST-stage cp.async pipeline, one barrier per k-tile.
// ABLEND=1: A operand synthesized in producer as blend(Pa,Pm,wsel) (GEMM1).
// mode 0: Ch = half(gelu(v+bias))
// mode 1: Ch = half(blend(Pa,Pm,wsel) + v + bias)
// mode 2: Cf = float(Rh) + v + bias

__device__ __forceinline__ void cp16(unsigned int s, const void* g){
    asm volatile("cp.async.cg.shared.global [%0], [%1], 16;\n" :: "r"(s), "l"(g));
}
__device__ __forceinline__ void ldm_x4(unsigned int* r, unsigned int a){
    asm volatile("ldmatrix.sync.aligned.m8n8.x4.shared.b16 {%0,%1,%2,%3}, [%4];"
                 : "=r"(r[0]), "=r"(r[1]), "=r"(r[2]), "=r"(r[3]) : "r"(a));
}
__device__ __forceinline__ void mma_f16(float* c, const unsigned int* a,
                                        unsigned int b0, unsigned int b1){
    asm volatile("mma.sync.aligned.m16n8k16.row.col.f32.f16.f16.f32 "
                 "{%0,%1,%2,%3}, {%4,%5,%6,%7}, {%8,%9}, {%0,%1,%2,%3};\n"
                 : "+f"(c[0]), "+f"(c[1]), "+f"(c[2]), "+f"(c[3])
                 : "r"(a[0]), "r"(a[1]), "r"(a[2]), "r"(a[3]), "r"(b0), "r"(b1));
}

template<int TM, int ST, int ABLEND>
__global__ void __launch_bounds__(256, 2) k_hgemm(
        const __half* __restrict__ A, const __half* __restrict__ W,
        const float* __restrict__ bias,
        __half* __restrict__ Ch,
        const __half* __restrict__ Pa, const __half* __restrict__ Pm,
        const float* __restrict__ wsel,
        const __half* __restrict__ Rh, float* __restrict__ Cf,
        int K, int N, int mode){
    constexpr int WMC = TM/32;
    constexpr int WNC = 8/WMC;
    constexpr int NT  = 128/WNC;
    constexpr int NF  = NT/8;
    constexpr int NFP = NT/16;
    constexpr int BOFF = TM*128;
    constexpr int STAGE = (TM + 128)*128;

    extern __shared__ __align__(16) char smem[];
    unsigned int smb = (unsigned int)__cvta_generic_to_shared(smem);

    const int tid = threadIdx.x, lane = tid & 31, warp = tid >> 5;
    const int wm = warp % WMC, wn = warp / WMC;
    const int qid = lane >> 2, tig = lane & 3;
    const int m0 = blockIdx.y*TM, n0 = blockIdx.x*128;
    const int nkt = K >> 6;

    float acc[2][NF][4];
    #pragma unroll
    for (int mf = 0; mf < 2; mf++)
        #pragma unroll
        for (int nf = 0; nf < NF; nf++)
            #pragma unroll
            for (int r = 0; r < 4; r++) acc[mf][nf][r] = 0.f;

    unsigned int qa[2], qb[NFP];
    {
        int ar = wm*32 + (lane & 15);
        int ahi = (lane >> 4) & 1;
        #pragma unroll
        for (int mf = 0; mf < 2; mf++){
            int row = ar + mf*16;
            qa[mf] = (unsigned int)(row*128 + ((ahi << 4) ^ ((row & 7) << 4)));
        }
        int bn = wn*NT + (lane & 7) + ((lane >> 4) & 1)*8;
        int bhi = (lane >> 3) & 1;
        #pragma unroll
        for (int nfp = 0; nfp < NFP; nfp++){
            int row = bn + nfp*16;
            qb[nfp] = (unsigned int)(BOFF + row*128 + ((bhi << 4) ^ ((row & 7) << 4)));
        }
    }

    auto load_tile = [&](int kt, int st){
        unsigned int sb = smb + st*STAGE;
        char* sbp = smem + st*STAGE;
        const __half* Ab = A + (size_t)m0*K + kt*64;
        const __half* Wb = W + (size_t)n0*K + kt*64;
        #pragma unroll
        for (int it = 0; it < TM/32; it++){
            int idx = tid + it*256;
            int row = idx >> 3, c = idx & 7;
            if (ABLEND){
                size_t goff = (size_t)(m0 + row)*K + kt*64 + c*8;
                float wv = wsel[(m0 + row) >> 7];
                uint4 av = *(const uint4*)(Pa + goff);
                uint4 mv = *(const uint4*)(Pm + goff);
                unsigned int o[4];
                const unsigned int* ap = (const unsigned int*)&av;
                const unsigned int* mp = (const unsigned int*)&mv;
                #pragma unroll
                for (int j = 0; j < 4; j++){
                    float2 af = __half22float2(*(const __half2*)&ap[j]);
                    float2 mf = __half22float2(*(const __half2*)&mp[j]);
                    __half2 r = __floats2half2_rn(fmaf(wv, af.x - mf.x, mf.x),
                                                  fmaf(wv, af.y - mf.y, mf.y));
                    o[j] = *(unsigned int*)&r;
                }
                *(uint4*)(sbp + row*128 + ((c ^ (row & 7)) << 4)) =
                    make_uint4(o[0], o[1], o[2], o[3]);
            } else {
                cp16(sb + row*128 + ((c ^ (row & 7)) << 4), Ab + (size_t)row*K + c*8);
            }
        }
        #pragma unroll
        for (int it = 0; it < 4; it++){
            int idx = tid + it*256;
            int row = idx >> 3, c = idx & 7;
            cp16(sb + BOFF + row*128 + ((c ^ (row & 7)) << 4), Wb + (size_t)row*K + c*8);
        }
        asm volatile("cp.async.commit_group;\n");
    };

    #pragma unroll
    for (int p = 0; p < ST-1; p++)
        if (p < nkt) load_tile(p, p);

    int st = 0;
    for (int kt = 0; kt < nkt; kt++){
        if (kt + ST-1 < nkt){
            asm volatile("cp.async.wait_group %0;\n" :: "n"(ST-2));
        } else {
            asm volatile("cp.async.wait_group %0;\n" :: "n"(0));
        }
        __syncthreads();
        if (kt + ST-1 < nkt){
            int s2 = st + ST-1; if (s2 >= ST) s2 -= ST;
            load_tile(kt + ST-1, s2);
        }

        unsigned int sb = smb + st*STAGE;
        #pragma unroll
        for (int ks = 0; ks < 4; ks++){
            unsigned int kx = (unsigned int)(ks << 5);
            unsigned int a[8], b[NFP*4];
            ldm_x4(a,     sb + (qa[0] ^ kx));
            ldm_x4(a + 4, sb + (qa[1] ^ kx));
            #pragma unroll
            for (int nfp = 0; nfp < NFP; nfp++)
                ldm_x4(b + nfp*4, sb + (qb[nfp] ^ kx));
            #pragma unroll
            for (int mf = 0; mf < 2; mf++)
                #pragma unroll
                for (int nf = 0; nf < NF; nf++)
                    mma_f16(acc[mf][nf], a + mf*4, b[nf*2], b[nf*2 + 1]);
        }
        if (++st == ST) st = 0;
    }

    // epilogue
    #pragma unroll
    for (int mf = 0; mf < 2; mf++){
        #pragma unroll
        for (int nf = 0; nf < NF; nf++){
            int col = n0 + wn*NT + nf*8 + tig*2;
            float2 bv = *(const float2*)(bias + col);
            #pragma unroll
            for (int h = 0; h < 2; h++){
                int row = m0 + wm*32 + mf*16 + qid + h*8;
                size_t idx = (size_t)row*N + col;
                float vx = acc[mf][nf][h*2 + 0] + bv.x;
                float vy = acc[mf][nf][h*2 + 1] + bv.y;
                if (mode == 0){
                    float ox = 0.5f*vx*(1.0f + erff(vx*0.70710678118f));
                    float oy = 0.5f*vy*(1.0f + erff(vy*0.70710678118f));
                    *(__half2*)(Ch + idx) = __floats2half2_rn(ox, oy);
                } else if (mode == 1){
                    float wv = wsel[row >> 7];
                    float2 af = __half22float2(*(const __half2*)(Pa + idx));
                    float2 mf2 = __half22float2(*(const __half2*)(Pm + idx));
                    float rx = fmaf(wv, af.x - mf2.x, mf2.x);
                    float ry = fmaf(wv, af.y - mf2.y, mf2.y);
                    *(__half2*)(Ch + idx) = __floats2half2_rn(rx + vx, ry + vy);
                } else {
                    float2 rf = __half22float2(*(const __half2*)(Rh + idx));
                    float2 o; o.x = rf.x + vx; o.y = rf.y + vy;
                    *(float2*)(Cf + idx) = o;
                }
            }
        }
    }
}

#define SMEM64  (4*((64 + 128)*128))    // 4-stage, 96KB
#define SMEM128 (3*((128 + 128)*128))   // 3-stage, 96KB

// ---------------- launch ----------------
extern "C" void kernel_launch(void* const* d_in, const int* in_sizes, int n_in,
                              void* d_out, int out_size){
    const float* x     = (const float*)d_in[0];
    const float* gamma = (const float*)d_in[1];
    const float* beta  = (const float*)d_in[2];
    float* out = (float*)d_out;

    cudaFuncSetAttribute((const void*)k_hgemm<64,4,0>,  cudaFuncAttributeMaxDynamicSharedMemorySize, SMEM64);
    cudaFuncSetAttribute((const void*)k_hgemm<64,4,1>,  cudaFuncAttributeMaxDynamicSharedMemorySize, SMEM64);
    cudaFuncSetAttribute((const void*)k_hgemm<128,3,0>, cudaFuncAttributeMaxDynamicSharedMemorySize, SMEM128);

    __half *ha1, *ha2, *hh, *hx, *hw;
    __half *pa0, *pm0, *pa1, *pm1, *pa2, *pm2;
    float *w3;
    cudaGetSymbolAddress((void**)&ha1, g_ha1);
    cudaGetSymbolAddress((void**)&ha2, g_ha2);
    cudaGetSymbolAddress((void**)&hh,  g_hh);
    cudaGetSymbolAddress((void**)&hx,  g_hx);
    cudaGetSymbolAddress((void**)&hw,  g_hw);
    cudaGetSymbolAddress((void**)&pa0, g_pa0);
    cudaGetSymbolAddress((void**)&pm0, g_pm0);
    cudaGetSymbolAddress((void**)&pa1, g_pa1);
    cudaGetSymbolAddress((void**)&pm1, g_pm1);
    cudaGetSymbolAddress((void**)&pa2, g_pa2);
    cudaGetSymbolAddress((void**)&pm2, g_pm2);
    cudaGetSymbolAddress((void**)&w3,  g_w3);
    static const size_t WOFF[6] = {0, 65536, 196608, 458752, 983040, 2031616};

    const float* lb1_0 = (const float*)d_in[3 + 0*8 + 5];
    const float* lb2_0 = (const float*)d_in[3 + 0*8 + 7];
    const float* lb1_1 = (const float*)d_in[3 + 1*8 + 5];
    const float* lb2_1 = (const float*)d_in[3 + 1*8 + 7];
    const float* lb1_2 = (const float*)d_in[3 + 2*8 + 5];
    const float* lb2_2 = (const float*)d_in[3 + 2*8 + 7];

    // launch 0: bn stats
    k_bnstats<<<(FS/4)/256, 256>>>((const float4*)x);
    // launch 1: fused bnapply + pools + stats
    k_bnpool<<<MR, 128>>>(x, gamma, beta);
    // launch 2: selectors
    k_selector3<<<192, 64>>>(
        (const float*)d_in[3 + 0*8 + 0], (const float*)d_in[3 + 1*8 + 0], (const float*)d_in[3 + 2*8 + 0],
        (const float*)d_in[3 + 0*8 + 1], (const float*)d_in[3 + 1*8 + 1], (const float*)d_in[3 + 2*8 + 1],
        (const float*)d_in[3 + 0*8 + 2], (const float*)d_in[3 + 1*8 + 2], (const float*)d_in[3 + 2*8 + 2],
        (const float*)d_in[3 + 0*8 + 3], (const float*)d_in[3 + 1*8 + 3], (const float*)d_in[3 + 2*8 + 3]);
    // launch 3 (ncu capture slot): weights -> half [N][K]
    k_wtrans_all<<<4032, dim3(32, 8)>>>(
        (const float*)d_in[3 + 0*8 + 4], (const float*)d_in[3 + 0*8 + 6],
        (const float*)d_in[3 + 1*8 + 4], (const float*)d_in[3 + 1*8 + 6],
        (const float*)d_in[3 + 2*8 + 4], (const float*)d_in[3 + 2*8 + 6]);

    // GEMM chain (GEMM1 blends its A operand from pa0/pm0 in the producer)
    k_hgemm<64,4,1> <<<dim3( 2, 128), 256, SMEM64 >>>(pa0, hw + WOFF[0], lb1_0, hh,  pa0, pm0, w3,     hx, out,  256,  256, 0);
    k_hgemm<64,4,0> <<<dim3( 4, 128), 256, SMEM64 >>>(hh,  hw + WOFF[1], lb2_0, ha1, pa1, pm1, w3+64,  hx, out,  256,  512, 1);
    k_hgemm<64,4,0> <<<dim3( 4, 128), 256, SMEM64 >>>(ha1, hw + WOFF[2], lb1_1, hh,  pa1, pm1, w3+64,  hx, out,  512,  512, 0);
    k_hgemm<128,3,0><<<dim3( 8,  64), 256, SMEM128>>>(hh,  hw + WOFF[3], lb2_1, ha2, pa2, pm2, w3+128, hx, out,  512, 1024, 1);
    k_hgemm<128,3,0><<<dim3( 8,  64), 256, SMEM128>>>(ha2, hw + WOFF[4], lb1_2, hh,  pa2, pm2, w3+128, hx, out, 1024, 1024, 0);
    k_hgemm<128,3,0><<<dim3(16,  64), 256, SMEM128>>>(hh,  hw + WOFF[5], lb2_2, hh,  pa2, pm2, w3+128, hx, out, 1024, 2048, 2);
}

// round 15
// speedup vs baseline: 1.1330x; 1.0344x over previous
#include <cuda_runtime.h>
#include <cuda_fp16.h>
#include <stdint.h>
#include <math.h>

#define BB 64
#define FF 128
#define SS 2048
#define FS (FF*SS)        // 262144
#define MR (BB*FF)        // 8192

// ---------------- scratch ----------------
__device__ float g_mu[FS];
__device__ float g_rstd[FS];
__device__ float g_stats3[3*BB*384];
__device__ float g_w3[3*BB];
__device__ __half g_pa0[MR*256];
__device__ __half g_pm0[MR*256];
__device__ __half g_pa1[MR*512];
__device__ __half g_pm1[MR*512];
__device__ __half g_pa2[MR*1024];
__device__ __half g_pm2[MR*1024];
__device__ __half g_ha1[MR*512];
__device__ __half g_ha2[MR*1024];
__device__ __half g_hh [MR*1024];
__device__ __half g_hx [MR*2048];   // normalized x, half (final residual base)
__device__ __half g_hw [4128768];   // 6 weights, transposed [N][K], half

// ---------------- combined preamble: bn stats (blocks 0..255) + weight transpose ----------------
__global__ void __launch_bounds__(256) k_pre(const float4* __restrict__ x,
        const float* w0, const float* w1, const float* w2,
        const float* w3, const float* w4, const float* w5){
    if (blockIdx.x < 256){
        int j = blockIdx.x*256 + threadIdx.x;        // over FS/4
        float4 s = make_float4(0,0,0,0), q = make_float4(0,0,0,0);
        #pragma unroll 4
        for (int b = 0; b < BB; b++){
            float4 v = x[(size_t)b*(FS/4) + j];
            s.x += v.x; s.y += v.y; s.z += v.z; s.w += v.w;
            q.x = fmaf(v.x, v.x, q.x); q.y = fmaf(v.y, v.y, q.y);
            q.z = fmaf(v.z, v.z, q.z); q.w = fmaf(v.w, v.w, q.w);
        }
        float4 mu, rs;
        mu.x = s.x*(1.0f/BB); mu.y = s.y*(1.0f/BB); mu.z = s.z*(1.0f/BB); mu.w = s.w*(1.0f/BB);
        rs.x = rsqrtf(fmaf(-mu.x, mu.x, q.x*(1.0f/BB)) + 1e-5f);
        rs.y = rsqrtf(fmaf(-mu.y, mu.y, q.y*(1.0f/BB)) + 1e-5f);
        rs.z = rsqrtf(fmaf(-mu.z, mu.z, q.z*(1.0f/BB)) + 1e-5f);
        rs.w = rsqrtf(fmaf(-mu.w, mu.w, q.w*(1.0f/BB)) + 1e-5f);
        ((float4*)g_mu)[j]   = mu;
        ((float4*)g_rstd)[j] = rs;
    } else {
        __shared__ float sm[32][33];
        int blk = blockIdx.x - 256;                  // 0..4031
        const float* in; __half* outp; int K, N, rem;
        if      (blk <   64){ in = w0; outp = g_hw;           K =  256; N =  256; rem = blk; }
        else if (blk <  192){ in = w1; outp = g_hw +   65536; K =  256; N =  512; rem = blk -   64; }
        else if (blk <  448){ in = w2; outp = g_hw +  196608; K =  512; N =  512; rem = blk -  192; }
        else if (blk <  960){ in = w3; outp = g_hw +  458752; K =  512; N = 1024; rem = blk -  448; }
        else if (blk < 1984){ in = w4; outp = g_hw +  983040; K = 1024; N = 1024; rem = blk -  960; }
        else                { in = w5; outp = g_hw + 2031616; K = 1024; N = 2048; rem = blk - 1984; }
        int tn = rem % (N/32), tk = rem / (N/32);
        int n0 = tn*32, k0 = tk*32;
        int tx = threadIdx.x & 31, ty = threadIdx.x >> 5;
        #pragma unroll
        for (int j = 0; j < 4; j++)
            sm[ty + j*8][tx] = in[(size_t)(k0 + ty + j*8)*N + n0 + tx];
        __syncthreads();
        #pragma unroll
        for (int j = 0; j < 4; j++)
            outp[(size_t)(n0 + ty + j*8)*K + k0 + tx] = __float2half(sm[tx][ty + j*8]);
    }
}

// ---------------- fused bnapply + pooling (half) + row stats (256 thr x 8 elem) ----------------
__global__ void __launch_bounds__(256) k_bnpool(const float* __restrict__ x,
        const float* __restrict__ gamma, const float* __restrict__ beta){
    int row = blockIdx.x, t = threadIdx.x;
    int b = row >> 7, f = row & 127;
    size_t gx = (size_t)b*FS + f*2048 + t*8;
    int    pj = f*2048 + t*8;

    float v[8];
    #pragma unroll
    for (int c = 0; c < 2; c++){
        float4 xv = *(const float4*)(x + gx + c*4);
        float4 mu = *(const float4*)(g_mu + pj + c*4);
        float4 rs = *(const float4*)(g_rstd + pj + c*4);
        float4 ga = *(const float4*)(gamma + pj + c*4);
        float4 be = *(const float4*)(beta + pj + c*4);
        v[c*4+0] = fmaf((xv.x - mu.x)*rs.x, ga.x, be.x);
        v[c*4+1] = fmaf((xv.y - mu.y)*rs.y, ga.y, be.y);
        v[c*4+2] = fmaf((xv.z - mu.z)*rs.z, ga.z, be.z);
        v[c*4+3] = fmaf((xv.w - mu.w)*rs.w, ga.w, be.w);
    }
    // normalized x -> half
    {
        __half2 h0 = __floats2half2_rn(v[0], v[1]), h1 = __floats2half2_rn(v[2], v[3]);
        __half2 h2 = __floats2half2_rn(v[4], v[5]), h3 = __floats2half2_rn(v[6], v[7]);
        *(uint4*)(g_hx + (size_t)row*2048 + t*8) =
            make_uint4(*(unsigned*)&h0, *(unsigned*)&h1, *(unsigned*)&h2, *(unsigned*)&h3);
    }

    float a2[4], m2[4];
    #pragma unroll
    for (int j = 0; j < 4; j++){
        a2[j] = 0.5f*(v[2*j] + v[2*j+1]);
        m2[j] = fmaxf(v[2*j], v[2*j+1]);
    }
    float a1[2], m1[2];
    #pragma unroll
    for (int j = 0; j < 2; j++){
        a1[j] = 0.5f*(a2[2*j] + a2[2*j+1]);
        m1[j] = fmaxf(m2[2*j], m2[2*j+1]);
    }
    float a0 = 0.5f*(a1[0] + a1[1]);
    float m0 = fmaxf(m1[0], m1[1]);

    {
        __half2 q0 = __floats2half2_rn(a2[0],a2[1]), q1 = __floats2half2_rn(a2[2],a2[3]);
        *(uint2*)(g_pa2 + (size_t)row*1024 + t*4) = make_uint2(*(unsigned*)&q0, *(unsigned*)&q1);
        __half2 r0 = __floats2half2_rn(m2[0],m2[1]), r1 = __floats2half2_rn(m2[2],m2[3]);
        *(uint2*)(g_pm2 + (size_t)row*1024 + t*4) = make_uint2(*(unsigned*)&r0, *(unsigned*)&r1);
        __half2 s1h = __floats2half2_rn(a1[0],a1[1]);
        *(unsigned*)(g_pa1 + (size_t)row*512 + t*2) = *(unsigned*)&s1h;
        __half2 u1h = __floats2half2_rn(m1[0],m1[1]);
        *(unsigned*)(g_pm1 + (size_t)row*512 + t*2) = *(unsigned*)&u1h;
        g_pa0[(size_t)row*256 + t] = __float2half(a0);
        g_pm0[(size_t)row*256 + t] = __float2half(m0);
    }

    float su[3], sq[3], mx[3];
    {
        float pv = 0.5f*(a0 + m0);
        su[0] = pv; sq[0] = pv*pv; mx[0] = pv;
    }
    su[1] = 0.f; sq[1] = 0.f; mx[1] = -3.4e38f;
    #pragma unroll
    for (int j = 0; j < 2; j++){
        float pv = 0.5f*(a1[j] + m1[j]);
        su[1] += pv; sq[1] = fmaf(pv, pv, sq[1]); mx[1] = fmaxf(mx[1], pv);
    }
    su[2] = 0.f; sq[2] = 0.f; mx[2] = -3.4e38f;
    #pragma unroll
    for (int j = 0; j < 4; j++){
        float pv = 0.5f*(a2[j] + m2[j]);
        su[2] += pv; sq[2] = fmaf(pv, pv, sq[2]); mx[2] = fmaxf(mx[2], pv);
    }

    __shared__ float red[8][9];
    int w = t >> 5, l = t & 31;
    #pragma unroll
    for (int s = 0; s < 3; s++){
        #pragma unroll
        for (int o = 16; o > 0; o >>= 1){
            su[s] += __shfl_down_sync(0xffffffffu, su[s], o);
            sq[s] += __shfl_down_sync(0xffffffffu, sq[s], o);
            mx[s]  = fmaxf(mx[s], __shfl_down_sync(0xffffffffu, mx[s], o));
        }
    }
    if (l == 0){
        #pragma unroll
        for (int s = 0; s < 3; s++){ red[w][s*3] = su[s]; red[w][s*3+1] = sq[s]; red[w][s*3+2] = mx[s]; }
    }
    __syncthreads();
    if (t == 0){
        #pragma unroll
        for (int s = 0; s < 3; s++){
            float S = 0.f, Q = 0.f, M = -3.4e38f;
            #pragma unroll
            for (int ww = 0; ww < 8; ww++){
                S += red[ww][s*3]; Q += red[ww][s*3+1]; M = fmaxf(M, red[ww][s*3+2]);
            }
            int L = 256 << s;
            float mean = S / (float)L;
            float var  = (Q - (float)L*mean*mean) / (float)(L - 1);
            float sd   = sqrtf(fmaxf(var, 0.f));
            float* st = g_stats3 + s*BB*384 + b*384;
            st[f] = mean; st[128 + f] = sd; st[256 + f] = M;
        }
    }
}

// ---------------- fused selector MLPs ----------------
__global__ void k_selector3(const float* w1a, const float* w1b, const float* w1c,
                            const float* b1a, const float* b1b, const float* b1c,
                            const float* w2a, const float* w2b, const float* w2c,
                            const float* b2a, const float* b2b, const float* b2c){
    int s = blockIdx.x >> 6, b = blockIdx.x & 63, t = threadIdx.x;
    const float* w1 = s==0 ? w1a : (s==1 ? w1b : w1c);
    const float* b1 = s==0 ? b1a : (s==1 ? b1b : b1c);
    const float* w2 = s==0 ? w2a : (s==1 ? w2b : w2c);
    const float* b2 = s==0 ? b2a : (s==1 ? b2b : b2c);
    const float* st = g_stats3 + s*BB*384 + b*384;
    float acc = b1[t];
    #pragma unroll 8
    for (int i = 0; i < 384; i++) acc = fmaf(st[i], w1[i*64 + t], acc);
    float hv = fmaxf(acc, 0.f) * w2[t];
    __shared__ float red[64];
    red[t] = hv;
    __syncthreads();
    if (t < 32){
        float v = red[t] + red[t + 32];
        #pragma unroll
        for (int o = 16; o > 0; o >>= 1) v += __shfl_down_sync(0xffffffffu, v, o);
        if (t == 0) g_w3[s*64 + b] = 1.0f / (1.0f + expf(-(v + b2[0])));
    }
}

// ---------------- fp16 tensor-core GEMM ----------------
// CTA TM x 128, 256 threads (8 warps), BK=64 halves, XOR-swizzled 128B rows,
// ST-stage cp.async pipeline, one barrier per k-tile.
// ABLEND=1: A operand synthesized in producer as blend(Pa,Pm,wsel) (GEMM1).
// mode 0: Ch = half(gelu(v+bias))
// mode 1: Ch = half(blend(Pa,Pm,wsel) + v + bias)
// mode 2: Cf = float(Rh) + v + bias

__device__ __forceinline__ void cp16(unsigned int s, const void* g){
    asm volatile("cp.async.cg.shared.global [%0], [%1], 16;\n" :: "r"(s), "l"(g));
}
__device__ __forceinline__ void ldm_x4(unsigned int* r, unsigned int a){
    asm volatile("ldmatrix.sync.aligned.m8n8.x4.shared.b16 {%0,%1,%2,%3}, [%4];"
                 : "=r"(r[0]), "=r"(r[1]), "=r"(r[2]), "=r"(r[3]) : "r"(a));
}
__device__ __forceinline__ void mma_f16(float* c, const unsigned int* a,
                                        unsigned int b0, unsigned int b1){
    asm volatile("mma.sync.aligned.m16n8k16.row.col.f32.f16.f16.f32 "
                 "{%0,%1,%2,%3}, {%4,%5,%6,%7}, {%8,%9}, {%0,%1,%2,%3};\n"
                 : "+f"(c[0]), "+f"(c[1]), "+f"(c[2]), "+f"(c[3])
                 : "r"(a[0]), "r"(a[1]), "r"(a[2]), "r"(a[3]), "r"(b0), "r"(b1));
}

template<int TM, int ST, int ABLEND>
__global__ void __launch_bounds__(256, 2) k_hgemm(
        const __half* __restrict__ A, const __half* __restrict__ W,
        const float* __restrict__ bias,
        __half* __restrict__ Ch,
        const __half* __restrict__ Pa, const __half* __restrict__ Pm,
        const float* __restrict__ wsel,
        const __half* __restrict__ Rh, float* __restrict__ Cf,
        int K, int N, int mode){
    constexpr int WMC = TM/32;
    constexpr int WNC = 8/WMC;
    constexpr int NT  = 128/WNC;
    constexpr int NF  = NT/8;
    constexpr int NFP = NT/16;
    constexpr int BOFF = TM*128;
    constexpr int STAGE = (TM + 128)*128;

    extern __shared__ __align__(16) char smem[];
    unsigned int smb = (unsigned int)__cvta_generic_to_shared(smem);

    const int tid = threadIdx.x, lane = tid & 31, warp = tid >> 5;
    const int wm = warp % WMC, wn = warp / WMC;
    const int qid = lane >> 2, tig = lane & 3;
    const int m0 = blockIdx.y*TM, n0 = blockIdx.x*128;
    const int nkt = K >> 6;

    float acc[2][NF][4];
    #pragma unroll
    for (int mf = 0; mf < 2; mf++)
        #pragma unroll
        for (int nf = 0; nf < NF; nf++)
            #pragma unroll
            for (int r = 0; r < 4; r++) acc[mf][nf][r] = 0.f;

    unsigned int qa[2], qb[NFP];
    {
        int ar = wm*32 + (lane & 15);
        int ahi = (lane >> 4) & 1;
        #pragma unroll
        for (int mf = 0; mf < 2; mf++){
            int row = ar + mf*16;
            qa[mf] = (unsigned int)(row*128 + ((ahi << 4) ^ ((row & 7) << 4)));
        }
        int bn = wn*NT + (lane & 7) + ((lane >> 4) & 1)*8;
        int bhi = (lane >> 3) & 1;
        #pragma unroll
        for (int nfp = 0; nfp < NFP; nfp++){
            int row = bn + nfp*16;
            qb[nfp] = (unsigned int)(BOFF + row*128 + ((bhi << 4) ^ ((row & 7) << 4)));
        }
    }

    auto load_tile = [&](int kt, int st){
        unsigned int sb = smb + st*STAGE;
        char* sbp = smem + st*STAGE;
        const __half* Ab = A + (size_t)m0*K + kt*64;
        const __half* Wb = W + (size_t)n0*K + kt*64;
        #pragma unroll
        for (int it = 0; it < TM/32; it++){
            int idx = tid + it*256;
            int row = idx >> 3, c = idx & 7;
            if (ABLEND){
                size_t goff = (size_t)(m0 + row)*K + kt*64 + c*8;
                float wv = wsel[(m0 + row) >> 7];
                uint4 av = *(const uint4*)(Pa + goff);
                uint4 mv = *(const uint4*)(Pm + goff);
                unsigned int o[4];
                const unsigned int* ap = (const unsigned int*)&av;
                const unsigned int* mp = (const unsigned int*)&mv;
                #pragma unroll
                for (int j = 0; j < 4; j++){
                    float2 af = __half22float2(*(const __half2*)&ap[j]);
                    float2 mf = __half22float2(*(const __half2*)&mp[j]);
                    __half2 r = __floats2half2_rn(fmaf(wv, af.x - mf.x, mf.x),
                                                  fmaf(wv, af.y - mf.y, mf.y));
                    o[j] = *(unsigned int*)&r;
                }
                *(uint4*)(sbp + row*128 + ((c ^ (row & 7)) << 4)) =
                    make_uint4(o[0], o[1], o[2], o[3]);
            } else {
                cp16(sb + row*128 + ((c ^ (row & 7)) << 4), Ab + (size_t)row*K + c*8);
            }
        }
        #pragma unroll
        for (int it = 0; it < 4; it++){
            int idx = tid + it*256;
            int row = idx >> 3, c = idx & 7;
            cp16(sb + BOFF + row*128 + ((c ^ (row & 7)) << 4), Wb + (size_t)row*K + c*8);
        }
        asm volatile("cp.async.commit_group;\n");
    };

    #pragma unroll
    for (int p = 0; p < ST-1; p++)
        if (p < nkt) load_tile(p, p);

    int st = 0;
    for (int kt = 0; kt < nkt; kt++){
        if (kt + ST-1 < nkt){
            asm volatile("cp.async.wait_group %0;\n" :: "n"(ST-2));
        } else {
            asm volatile("cp.async.wait_group %0;\n" :: "n"(0));
        }
        __syncthreads();
        if (kt + ST-1 < nkt){
            int s2 = st + ST-1; if (s2 >= ST) s2 -= ST;
            load_tile(kt + ST-1, s2);
        }

        unsigned int sb = smb + st*STAGE;
        #pragma unroll
        for (int ks = 0; ks < 4; ks++){
            unsigned int kx = (unsigned int)(ks << 5);
            unsigned int a[8], b[NFP*4];
            ldm_x4(a,     sb + (qa[0] ^ kx));
            ldm_x4(a + 4, sb + (qa[1] ^ kx));
            #pragma unroll
            for (int nfp = 0; nfp < NFP; nfp++)
                ldm_x4(b + nfp*4, sb + (qb[nfp] ^ kx));
            #pragma unroll
            for (int mf = 0; mf < 2; mf++)
                #pragma unroll
                for (int nf = 0; nf < NF; nf++)
                    mma_f16(acc[mf][nf], a + mf*4, b[nf*2], b[nf*2 + 1]);
        }
        if (++st == ST) st = 0;
    }

    // epilogue
    #pragma unroll
    for (int mf = 0; mf < 2; mf++){
        #pragma unroll
        for (int nf = 0; nf < NF; nf++){
            int col = n0 + wn*NT + nf*8 + tig*2;
            float2 bv = *(const float2*)(bias + col);
            #pragma unroll
            for (int h = 0; h < 2; h++){
                int row = m0 + wm*32 + mf*16 + qid + h*8;
                size_t idx = (size_t)row*N + col;
                float vx = acc[mf][nf][h*2 + 0] + bv.x;
                float vy = acc[mf][nf][h*2 + 1] + bv.y;
                if (mode == 0){
                    float ox = 0.5f*vx*(1.0f + erff(vx*0.70710678118f));
                    float oy = 0.5f*vy*(1.0f + erff(vy*0.70710678118f));
                    *(__half2*)(Ch + idx) = __floats2half2_rn(ox, oy);
                } else if (mode == 1){
                    float wv = wsel[row >> 7];
                    float2 af = __half22float2(*(const __half2*)(Pa + idx));
                    float2 mf2 = __half22float2(*(const __half2*)(Pm + idx));
                    float rx = fmaf(wv, af.x - mf2.x, mf2.x);
                    float ry = fmaf(wv, af.y - mf2.y, mf2.y);
                    *(__half2*)(Ch + idx) = __floats2half2_rn(rx + vx, ry + vy);
                } else {
                    float2 rf = __half22float2(*(const __half2*)(Rh + idx));
                    float2 o; o.x = rf.x + vx; o.y = rf.y + vy;
                    *(float2*)(Cf + idx) = o;
                }
            }
        }
    }
}

#define SMEM64  (4*((64 + 128)*128))    // 4-stage, 96KB
#define SMEM128 (3*((128 + 128)*128))   // 3-stage, 96KB

// ---------------- launch ----------------
extern "C" void kernel_launch(void* const* d_in, const int* in_sizes, int n_in,
                              void* d_out, int out_size){
    const float* x     = (const float*)d_in[0];
    const float* gamma = (const float*)d_in[1];
    const float* beta  = (const float*)d_in[2];
    float* out = (float*)d_out;

    cudaFuncSetAttribute((const void*)k_hgemm<64,4,0>,  cudaFuncAttributeMaxDynamicSharedMemorySize, SMEM64);
    cudaFuncSetAttribute((const void*)k_hgemm<64,4,1>,  cudaFuncAttributeMaxDynamicSharedMemorySize, SMEM64);
    cudaFuncSetAttribute((const void*)k_hgemm<128,3,0>, cudaFuncAttributeMaxDynamicSharedMemorySize, SMEM128);

    __half *ha1, *ha2, *hh, *hx, *hw;
    __half *pa0, *pm0, *pa1, *pm1, *pa2, *pm2;
    float *w3;
    cudaGetSymbolAddress((void**)&ha1, g_ha1);
    cudaGetSymbolAddress((void**)&ha2, g_ha2);
    cudaGetSymbolAddress((void**)&hh,  g_hh);
    cudaGetSymbolAddress((void**)&hx,  g_hx);
    cudaGetSymbolAddress((void**)&hw,  g_hw);
    cudaGetSymbolAddress((void**)&pa0, g_pa0);
    cudaGetSymbolAddress((void**)&pm0, g_pm0);
    cudaGetSymbolAddress((void**)&pa1, g_pa1);
    cudaGetSymbolAddress((void**)&pm1, g_pm1);
    cudaGetSymbolAddress((void**)&pa2, g_pa2);
    cudaGetSymbolAddress((void**)&pm2, g_pm2);
    cudaGetSymbolAddress((void**)&w3,  g_w3);
    static const size_t WOFF[6] = {0, 65536, 196608, 458752, 983040, 2031616};

    const float* lb1_0 = (const float*)d_in[3 + 0*8 + 5];
    const float* lb2_0 = (const float*)d_in[3 + 0*8 + 7];
    const float* lb1_1 = (const float*)d_in[3 + 1*8 + 5];
    const float* lb2_1 = (const float*)d_in[3 + 1*8 + 7];
    const float* lb1_2 = (const float*)d_in[3 + 2*8 + 5];
    const float* lb2_2 = (const float*)d_in[3 + 2*8 + 7];

    // launch 0: bn stats + weight transpose (independent, co-resident)
    k_pre<<<256 + 4032, 256>>>((const float4*)x,
        (const float*)d_in[3 + 0*8 + 4], (const float*)d_in[3 + 0*8 + 6],
        (const float*)d_in[3 + 1*8 + 4], (const float*)d_in[3 + 1*8 + 6],
        (const float*)d_in[3 + 2*8 + 4], (const float*)d_in[3 + 2*8 + 6]);
    // launch 1: fused bnapply + pools + stats
    k_bnpool<<<MR, 256>>>(x, gamma, beta);
    // launch 2: selectors
    k_selector3<<<192, 64>>>(
        (const float*)d_in[3 + 0*8 + 0], (const float*)d_in[3 + 1*8 + 0], (const float*)d_in[3 + 2*8 + 0],
        (const float*)d_in[3 + 0*8 + 1], (const float*)d_in[3 + 1*8 + 1], (const float*)d_in[3 + 2*8 + 1],
        (const float*)d_in[3 + 0*8 + 2], (const float*)d_in[3 + 1*8 + 2], (const float*)d_in[3 + 2*8 + 2],
        (const float*)d_in[3 + 0*8 + 3], (const float*)d_in[3 + 1*8 + 3], (const float*)d_in[3 + 2*8 + 3]);

    // GEMM chain (GEMM1 blends its A operand from pa0/pm0 in the producer)
    k_hgemm<64,4,1> <<<dim3( 2, 128), 256, SMEM64 >>>(pa0, hw + WOFF[0], lb1_0, hh,  pa0, pm0, w3,     hx, out,  256,  256, 0);
    k_hgemm<64,4,0> <<<dim3( 4, 128), 256, SMEM64 >>>(hh,  hw + WOFF[1], lb2_0, ha1, pa1, pm1, w3+64,  hx, out,  256,  512, 1);
    k_hgemm<64,4,0> <<<dim3( 4, 128), 256, SMEM64 >>>(ha1, hw + WOFF[2], lb1_1, hh,  pa1, pm1, w3+64,  hx, out,  512,  512, 0);
    k_hgemm<128,3,0><<<dim3( 8,  64), 256, SMEM128>>>(hh,  hw + WOFF[3], lb2_1, ha2, pa2, pm2, w3+128, hx, out,  512, 1024, 1);
    k_hgemm<128,3,0><<<dim3( 8,  64), 256, SMEM128>>>(ha2, hw + WOFF[4], lb1_2, hh,  pa2, pm2, w3+128, hx, out, 1024, 1024, 0);
    k_hgemm<128,3,0><<<dim3(16,  64), 256, SMEM128>>>(hh,  hw + WOFF[5], lb2_2, hh,  pa2, pm2, w3+128, hx, out, 1024, 2048, 2);
}